// round 2
// baseline (speedup 1.0000x reference)
#include <cuda_runtime.h>

#define NB 16384
#define NT 60
#define ND 36
#define NL 10
#define NC 20
#define NS 9
#define NO 8
#define KG (NL + ND)      // 46
#define KE (NL + NC)      // 30
#define MIN_ (NT*NL + NS) // 609

__device__ __forceinline__ float sigf(float x) {
    // 1/(1+exp(-x)); __expf + fast divide, ~1e-7 rel err
    return __fdividef(1.f, 1.f + __expf(-x));
}
__device__ __forceinline__ float tanhfast(float x) {
    // tanh(x) = 1 - 2/(exp(2x)+1); stable at +-inf, ~1e-6 abs err
    float e = __expf(2.f * x);
    return 1.f - __fdividef(2.f, e + 1.f);
}

struct __align__(16) SW {
    float Wu[KG][12];     // padded rows (10 -> 12 floats) for LDS.128 alignment
    float Wr[KG][12];
    float Wn[KG][12];
    float We[KE][NC];     // 20 floats = 80B, aligned
    float Wo[NL][12];
    float Wm[MIN_][NO];   // 8 floats = 32B, aligned
    float bu[12], br[12], bn[12], bo[12];
    float be[NC];
    float bm[NO];
    float dts[NT];
};

__global__ __launch_bounds__(128) void dgm2_kernel(
    const float* __restrict__ data,
    const float* __restrict__ ts,
    const float* __restrict__ stat,
    const float* __restrict__ gWu, const float* __restrict__ gbu,
    const float* __restrict__ gWr, const float* __restrict__ gbr,
    const float* __restrict__ gWn, const float* __restrict__ gbn,
    const float* __restrict__ gWe, const float* __restrict__ gbe,
    const float* __restrict__ gWo, const float* __restrict__ gbo,
    const float* __restrict__ gWm, const float* __restrict__ gbm,
    float* __restrict__ out)
{
    __shared__ SW sw;
    const int tid = threadIdx.x;

    // ---- stage weights into shared (padded rows) ----
    for (int i = tid; i < KG * NL; i += 128) {
        int r = i / NL, c = i - r * NL;
        sw.Wu[r][c] = gWu[i];
        sw.Wr[r][c] = gWr[i];
        sw.Wn[r][c] = gWn[i];
    }
    for (int i = tid; i < KE * NC; i += 128) sw.We[i / NC][i % NC] = gWe[i];
    for (int i = tid; i < NL * NL; i += 128) sw.Wo[i / NL][i % NL] = gWo[i];
    for (int i = tid; i < MIN_ * NO; i += 128) (&sw.Wm[0][0])[i] = gWm[i];
    if (tid < NL) {
        sw.bu[tid] = gbu[tid];
        sw.br[tid] = gbr[tid];
        sw.bn[tid] = gbn[tid];
        sw.bo[tid] = gbo[tid];
    }
    if (tid < NC) sw.be[tid] = gbe[tid];
    if (tid < NO) sw.bm[tid] = gbm[tid];
    if (tid < NT) sw.dts[tid] = (tid == 0) ? 0.01f : (ts[tid] - ts[tid - 1]);
    __syncthreads();

    const int b = blockIdx.x * 128 + tid;

    // ---- per-trajectory carried state ----
    float y[NL], pr[NC], acc[NO];
#pragma unroll
    for (int j = 0; j < NL; j++) y[j] = 0.f;
#pragma unroll
    for (int c = 0; c < NC; c++) pr[c] = 0.f;
#pragma unroll
    for (int o = 0; o < NO; o++) acc[o] = 0.f;

    const float4* xptr = reinterpret_cast<const float4*>(data + (size_t)b * NT * ND);
    float4 xc[9], xn[9];
#pragma unroll
    for (int i = 0; i < 9; i++) xc[i] = xptr[i];

#pragma unroll 1
    for (int t = 0; t < NT; t++) {
        // prefetch next step's x while computing this step
        if (t + 1 < NT) {
            const float4* p = xptr + (t + 1) * 9;
#pragma unroll
            for (int i = 0; i < 9; i++) xn[i] = p[i];
        }
        float x[ND];
#pragma unroll
        for (int i = 0; i < 9; i++) {
            x[4 * i + 0] = xc[i].x; x[4 * i + 1] = xc[i].y;
            x[4 * i + 2] = xc[i].z; x[4 * i + 3] = xc[i].w;
        }
        const float dt = sw.dts[t];

        // ---- ODE Euler: yo = y + tanh(y@Wo + bo) * dt ----
        float og[NL];
#pragma unroll
        for (int j = 0; j < NL; j++) og[j] = sw.bo[j];
#pragma unroll
        for (int k = 0; k < NL; k++) {
            float yv = y[k];
#pragma unroll
            for (int j = 0; j < NL; j++) og[j] += yv * sw.Wo[k][j];
        }
        float yo[NL];
#pragma unroll
        for (int j = 0; j < NL; j++) yo[j] = y[j] + tanhfast(og[j]) * dt;

        // ---- GRU gates: yc = [yo, x] ----
        float au[NL], ar[NL], an[NL];
#pragma unroll
        for (int j = 0; j < NL; j++) {
            au[j] = sw.bu[j]; ar[j] = sw.br[j]; an[j] = sw.bn[j];
        }
        // x part (shared by all three gates)
#pragma unroll
        for (int k = 0; k < ND; k++) {
            float xv = x[k];
#pragma unroll
            for (int j = 0; j < NL; j++) {
                au[j] += xv * sw.Wu[NL + k][j];
                ar[j] += xv * sw.Wr[NL + k][j];
                an[j] += xv * sw.Wn[NL + k][j];
            }
        }
        // yo part for update/reset
#pragma unroll
        for (int k = 0; k < NL; k++) {
            float yv = yo[k];
#pragma unroll
            for (int j = 0; j < NL; j++) {
                au[j] += yv * sw.Wu[k][j];
                ar[j] += yv * sw.Wr[k][j];
            }
        }
        float u[NL], r[NL];
#pragma unroll
        for (int j = 0; j < NL; j++) { u[j] = sigf(au[j]); r[j] = sigf(ar[j]); }
        // (yo * r) part for candidate
#pragma unroll
        for (int k = 0; k < NL; k++) {
            float cv = yo[k] * r[k];
#pragma unroll
            for (int j = 0; j < NL; j++) an[j] += cv * sw.Wn[k][j];
        }
        float yn[NL];
#pragma unroll
        for (int j = 0; j < NL; j++) yn[j] = an[j] + u[j] * (yo[j] - an[j]);

        // ---- emit softmax: zin = [pr, yn] ----
        float lg[NC];
#pragma unroll
        for (int c = 0; c < NC; c++) lg[c] = sw.be[c];
#pragma unroll
        for (int k = 0; k < NC; k++) {
            float pv = pr[k];
#pragma unroll
            for (int c = 0; c < NC; c++) lg[c] += pv * sw.We[k][c];
        }
#pragma unroll
        for (int k = 0; k < NL; k++) {
            float yv = yn[k];
#pragma unroll
            for (int c = 0; c < NC; c++) lg[c] += yv * sw.We[NC + k][c];
        }
        float ssum = 0.f;
#pragma unroll
        for (int c = 0; c < NC; c++) { float e = __expf(lg[c]); pr[c] = e; ssum += e; }
        float inv = __fdividef(1.f, ssum);
#pragma unroll
        for (int c = 0; c < NC; c++) pr[c] *= inv;

        // ---- fused MLP accumulation for this step's state ----
        const float* wm = &sw.Wm[t * NL][0];
#pragma unroll
        for (int l = 0; l < NL; l++) {
            float yv = yn[l];
#pragma unroll
            for (int o = 0; o < NO; o++) acc[o] += yv * wm[l * NO + o];
        }

        // carry
#pragma unroll
        for (int j = 0; j < NL; j++) y[j] = yn[j];
#pragma unroll
        for (int i = 0; i < 9; i++) xc[i] = xn[i];
    }

    // ---- static part + bias ----
    const float* sp = stat + b * NS;
#pragma unroll
    for (int s = 0; s < NS; s++) {
        float sv = sp[s];
#pragma unroll
        for (int o = 0; o < NO; o++) acc[o] += sv * sw.Wm[NT * NL + s][o];
    }
    float* op = out + b * NO;
#pragma unroll
    for (int o = 0; o < NO; o++) op[o] = acc[o] + sw.bm[o];
}

extern "C" void kernel_launch(void* const* d_in, const int* in_sizes, int n_in,
                              void* d_out, int out_size) {
    dgm2_kernel<<<128, 128>>>(
        (const float*)d_in[0],   // data
        (const float*)d_in[1],   // time_steps
        (const float*)d_in[2],   // static_data
        (const float*)d_in[3],  (const float*)d_in[4],   // W_update, b_update
        (const float*)d_in[5],  (const float*)d_in[6],   // W_reset, b_reset
        (const float*)d_in[7],  (const float*)d_in[8],   // W_new, b_new
        (const float*)d_in[9],  (const float*)d_in[10],  // W_emit, b_emit
        (const float*)d_in[11], (const float*)d_in[12],  // W_ode, b_ode
        (const float*)d_in[13], (const float*)d_in[14],  // W_mlp, b_mlp
        (float*)d_out);
}